// round 17
// baseline (speedup 1.0000x reference)
#include <cuda_runtime.h>

// FFT convolution (S4): y[b,0,h,:] = first 4096 samples of linear conv(x[b,h,:], k[0,h,:])
// via length-8192 real FFT implemented as 4096-pt complex FFT with even/odd packing.
//
// R16: unified pointwise enumeration — 1920 main pairs + 127 boundary pairs + DC = 2048
// units = exactly 8 iterations x 256 threads. Pair smem byte-offsets precomputed into a
// 16 KB g_idx table (kills per-iteration digit/PHI arithmetic); boundary folded into the
// same PQS tables. Everything else = R15 (folded pointwise operator, h-adjacent CTA
// scheduling, gmem-direct first/last stages, stage-twiddle tables, packed f32x2, occ 4).

#define M 4096
#define H 1024
#define B 4
#define NT 256
#define NPAIR 1920
#define NUNIT 2048

#define PHI(a) ((a) ^ (((a) >> 4) & 15) ^ ((((a) >> 8) & 15) << 4))

typedef unsigned long long C;

__device__ C g_idx[NUNIT];               // packed {PHI(p)<<3, PHI(q)<<3}
__device__ float2 g_twU2[NUNIT];         // e^{-pi i kk(t) / M} (kf only)
__device__ float2 g_twS1[15 * 256];      // [(m-1)*256 + t] = e^{-2pi i m t / 4096}
__device__ float2 g_twS2[15 * 16];       // [(m-1)*16 + j]   = e^{-2pi i m j / 256}
__device__ ulonglong2 g_KfPQ[H * NUNIT]; // {P, Q}; entry 2047 = {(Kf0.re,KfM.re), Kf[M/2]}
__device__ C g_KfS[H * NUNIT];           // S

// ---------------- packed complex: lo 32 bits = re, hi 32 bits = im ---------------------
__device__ __forceinline__ C packC(float re, float im) {
    C r; asm("mov.b64 %0, {%1, %2};" : "=l"(r) : "f"(re), "f"(im)); return r;
}
__device__ __forceinline__ void unpackC(C a, float& re, float& im) {
    asm("mov.b64 {%0, %1}, %2;" : "=f"(re), "=f"(im) : "l"(a));
}
__device__ __forceinline__ C padd(C a, C b) {
    C r; asm("add.rn.f32x2 %0, %1, %2;" : "=l"(r) : "l"(a), "l"(b)); return r;
}
__device__ __forceinline__ C pmul(C a, C b) {
    C r; asm("mul.rn.f32x2 %0, %1, %2;" : "=l"(r) : "l"(a), "l"(b)); return r;
}
__device__ __forceinline__ C pfma(C a, C b, C c) {
    C r; asm("fma.rn.f32x2 %0, %1, %2, %3;" : "=l"(r) : "l"(a), "l"(b), "l"(c)); return r;
}
__device__ __forceinline__ C psub(C a, C b) {           // a - b = fma(b, -1, a)
    return pfma(b, 0xBF800000BF800000ULL, a);
}
__device__ __forceinline__ C swapC(C a) {               // (im, re)
    unsigned lo, hi; asm("mov.b64 {%0, %1}, %2;" : "=r"(lo), "=r"(hi) : "l"(a));
    C r; asm("mov.b64 %0, {%1, %2};" : "=l"(r) : "r"(hi), "r"(lo)); return r;
}
__device__ __forceinline__ C conjC(C a)  { return a ^ 0x8000000000000000ULL; }
__device__ __forceinline__ C negconjC(C a) { return a ^ 0x0000000080000000ULL; }  // -conj(a)
__device__ __forceinline__ C muli(C a)   { return swapC(a) ^ 0x80000000ULL; }
__device__ __forceinline__ C mulmi(C a)  { return swapC(a) ^ 0x8000000000000000ULL; }
__device__ __forceinline__ C splat_re(C a) {
    unsigned lo, hi; asm("mov.b64 {%0, %1}, %2;" : "=r"(lo), "=r"(hi) : "l"(a));
    C r; asm("mov.b64 %0, {%1, %2};" : "=l"(r) : "r"(lo), "r"(lo)); return r;
}
__device__ __forceinline__ C splat_im(C a) {
    unsigned lo, hi; asm("mov.b64 {%0, %1}, %2;" : "=r"(lo), "=r"(hi) : "l"(a));
    C r; asm("mov.b64 %0, {%1, %2};" : "=l"(r) : "r"(hi), "r"(hi)); return r;
}
__device__ __forceinline__ C cmul(C a, C b) {
    return pfma(splat_im(a), muli(b), pmul(splat_re(a), b));
}
__device__ __forceinline__ C cmul_acc(C a, C b, C acc) {   // a*b + acc
    return pfma(splat_im(a), muli(b), pfma(splat_re(a), b, acc));
}
__device__ __forceinline__ C cmulc(C a, C b) { return cmul(a, conjC(b)); }
__device__ __forceinline__ C cmulK(C a, float cr, float ci) {
    return pfma(splat_im(a), packC(-ci, cr), pmul(splat_re(a), packC(cr, ci)));
}

#define CC 0.70710678118654752f
#define HALFC 0x3F0000003F000000ULL     // (0.5, 0.5)
#define SCALEC 0x3980000039800000ULL    // (2^-12, 2^-12) = 1/M

// cos/sin(k*pi/8)
__device__ __forceinline__ constexpr float w16c(int k) {
    return (k == 0) ? 1.f : (k == 1) ? 0.9238795325112867f : (k == 2) ? 0.7071067811865476f
         : (k == 3) ? 0.3826834323650898f : (k == 4) ? 0.f : (k == 5) ? -0.3826834323650898f
         : (k == 6) ? -0.7071067811865476f : (k == 7) ? -0.9238795325112867f
         : (k == 8) ? -1.f : -0.9238795325112867f;
}
__device__ __forceinline__ constexpr float w16s(int k) {
    return (k == 0) ? 0.f : (k == 1) ? 0.3826834323650898f : (k == 2) ? 0.7071067811865476f
         : (k == 3) ? 0.9238795325112867f : (k == 4) ? 1.f : (k == 5) ? 0.9238795325112867f
         : (k == 6) ? 0.7071067811865476f : (k == 7) ? 0.3826834323650898f
         : (k == 8) ? 0.f : -0.3826834323650898f;
}

// unified unit t -> (kk, p, q).  t<1920: main pairs; 1920..2046: boundary u=t-1919;
// t==2047: DC special (p=0, q=8 placeholders).
__device__ __forceinline__ void unit_params(int t, int& kk, int& p, int& q) {
    if (t < NPAIR) {
        int c0 = 1 + (t >> 7);
        int c1 = t & 15;
        int c2 = (t >> 4) & 7;
        kk = 256 * c2 + 16 * c1 + c0;
        p = 256 * c0 + 16 * c1 + c2;
        q = 4351 - p;
    } else if (t < NUNIT - 1) {
        int u = t - 1919;                       // 1..127
        kk = 16 * u;
        p = 16 * (u & 15) + (u >> 4);
        int w = 256 - u;
        q = 16 * (w & 15) + ((w >> 4) & 15);
    } else {
        kk = 0; p = 0; q = 8;
    }
}

__global__ void init_twiddles() {
    int i = blockIdx.x * blockDim.x + threadIdx.x;
    if (i < NUNIT) {
        int kk, p, q;
        unit_params(i, kk, p, q);
        g_idx[i] = (C)(unsigned)(PHI(p) << 3) | ((C)(unsigned)(PHI(q) << 3) << 32);
        float s, c;
        sincospif(-(float)kk / (float)M, &s, &c);
        g_twU2[i] = make_float2(c, s);
    }
    int i2 = i - NUNIT;
    if (i2 >= 0 && i2 < 15 * 256) {
        int m = (i2 >> 8) + 1, tt = i2 & 255;
        float s, c;
        sincospif(-2.0f * (float)(m * tt) / 4096.0f, &s, &c);
        g_twS1[i2] = make_float2(c, s);
    }
    int i3 = i - NUNIT - 15 * 256;
    if (i3 >= 0 && i3 < 15 * 16) {
        int m = (i3 >> 4) + 1, j = i3 & 15;
        float s, c;
        sincospif(-2.0f * (float)(m * j) / 256.0f, &s, &c);
        g_twS2[i3] = make_float2(c, s);
    }
}

// ---------------- DFT building blocks --------------------------------------------------

template <bool FWD>
__device__ __forceinline__ void dft4(C& A, C& Bv, C& Cv, C& D) {
    C t0 = padd(A, Cv), t1 = psub(A, Cv), t2 = padd(Bv, D), t3 = psub(Bv, D);
    A = padd(t0, t2); Cv = psub(t0, t2);
    C j = FWD ? mulmi(t3) : muli(t3);
    Bv = padd(t1, j); D = psub(t1, j);
}

template <bool FWD, int E>
__device__ __forceinline__ C cw16(C a) {
    if (E == 4) return FWD ? mulmi(a) : muli(a);
    return cmulK(a, w16c(E), FWD ? -w16s(E) : w16s(E));
}

// natural input, output X[m] at slot perm(m) = ((m&3)<<2)|(m>>2)
template <bool FWD>
__device__ __forceinline__ void dft16(C* r) {
    dft4<FWD>(r[0], r[4], r[8], r[12]);
    dft4<FWD>(r[1], r[5], r[9], r[13]);
    dft4<FWD>(r[2], r[6], r[10], r[14]);
    dft4<FWD>(r[3], r[7], r[11], r[15]);
    r[5]  = cw16<FWD, 1>(r[5]);
    r[9]  = cw16<FWD, 2>(r[9]);
    r[13] = cw16<FWD, 3>(r[13]);
    r[6]  = cw16<FWD, 2>(r[6]);
    r[10] = cw16<FWD, 4>(r[10]);
    r[14] = cw16<FWD, 6>(r[14]);
    r[7]  = cw16<FWD, 3>(r[7]);
    r[11] = cw16<FWD, 6>(r[11]);
    r[15] = cw16<FWD, 9>(r[15]);
    dft4<FWD>(r[0],  r[1],  r[2],  r[3]);
    dft4<FWD>(r[4],  r[5],  r[6],  r[7]);
    dft4<FWD>(r[8],  r[9],  r[10], r[11]);
    dft4<FWD>(r[12], r[13], r[14], r[15]);
}
#define X16(r, m) (r)[(((m) & 3) << 2) | ((m) >> 2)]

__device__ __forceinline__ void dft8f(C* a) {
    C s0 = padd(a[0], a[4]), s1 = psub(a[0], a[4]), s2 = padd(a[2], a[6]), s3 = psub(a[2], a[6]);
    C E0 = padd(s0, s2), E2 = psub(s0, s2);
    C js = mulmi(s3);
    C E1 = padd(s1, js), E3 = psub(s1, js);
    C t0 = padd(a[1], a[5]), t1 = psub(a[1], a[5]), t2 = padd(a[3], a[7]), t3 = psub(a[3], a[7]);
    C O0 = padd(t0, t2), O2 = psub(t0, t2);
    C jt = mulmi(t3);
    C O1 = padd(t1, jt), O3 = psub(t1, jt);
    const C CC2 = packC(CC, CC);
    C P1 = pmul(CC2, padd(mulmi(O1), O1));
    C P2 = mulmi(O2);
    C P3 = pmul(CC2, psub(mulmi(O3), O3));
    a[0] = padd(E0, O0); a[4] = psub(E0, O0);
    a[1] = padd(E1, P1); a[5] = psub(E1, P1);
    a[2] = padd(E2, P2); a[6] = psub(E2, P2);
    a[3] = padd(E3, P3); a[7] = psub(E3, P3);
}

__device__ __forceinline__ void dft8i(C* a) {
    C s0 = padd(a[0], a[4]), s1 = psub(a[0], a[4]), s2 = padd(a[2], a[6]), s3 = psub(a[2], a[6]);
    C E0 = padd(s0, s2), E2 = psub(s0, s2);
    C js = muli(s3);
    C E1 = padd(s1, js), E3 = psub(s1, js);
    C t0 = padd(a[1], a[5]), t1 = psub(a[1], a[5]), t2 = padd(a[3], a[7]), t3 = psub(a[3], a[7]);
    C O0 = padd(t0, t2), O2 = psub(t0, t2);
    C jt = muli(t3);
    C O1 = padd(t1, jt), O3 = psub(t1, jt);
    const C CC2 = packC(CC, CC);
    C P1 = pmul(CC2, padd(muli(O1), O1));
    C P2 = muli(O2);
    C P3 = pmul(CC2, psub(muli(O3), O3));
    a[0] = padd(E0, O0); a[4] = psub(E0, O0);
    a[1] = padd(E1, P1); a[5] = psub(E1, P1);
    a[2] = padd(E2, P2); a[6] = psub(E2, P2);
    a[3] = padd(E3, P3); a[7] = psub(E3, P3);
}

#define TWS1 ((const C*)g_twS1)
#define TWS2 ((const C*)g_twS2)
#define TWU2 ((const C*)g_twU2)

// ---------------- stages (NT=256, 1 butterfly per thread per stage) --------------------

// fwd L=4096 (q=256): loads x DIRECTLY from gmem (logical t+256k, k<8; upper half of
// the zero-padded input is pruned), stores to swizzled smem. Twiddles from g_twS1.
__device__ __forceinline__ void fwd_stage1(C* __restrict__ z, const C* __restrict__ src, int t) {
    const int d0 = t & 15, d1 = (t >> 4) & 15;
    const int Cb = (d0 ^ d1) | (d1 << 4);
    C a[8], b[8];
#pragma unroll
    for (int k = 0; k < 8; k++) a[k] = src[t + (k << 8)];
    b[0] = a[0];
#pragma unroll
    for (int k = 1; k < 8; k++) b[k] = cmulK(a[k], w16c(k), -w16s(k));
    dft8f(a);   // X[2r]
    dft8f(b);   // X[2r+1]
    z[Cb] = a[0];
#define ST1(m) z[Cb ^ (((m) << 4) ^ ((m) << 8))] = cmul(((m) & 1) ? b[(m) >> 1] : a[(m) >> 1], TWS1[((m) - 1) * 256 + t])
    ST1(1); ST1(2); ST1(3); ST1(4); ST1(5); ST1(6); ST1(7); ST1(8);
    ST1(9); ST1(10); ST1(11); ST1(12); ST1(13); ST1(14); ST1(15);
#undef ST1
}

// fwd L=256 (q=16); twiddles from g_twS2
__device__ __forceinline__ void fwd_stage2(C* __restrict__ z, int t) {
    const int bb = t >> 4, j = t & 15;
    const int Cb = j | (bb << 4) | (bb << 8);
    C r[16];
#pragma unroll
    for (int k = 0; k < 16; k++) r[k] = z[Cb ^ (17 * k)];
    dft16<true>(r);
    z[Cb] = r[0];
#define ST2(m) z[Cb ^ (17 * (m))] = cmul(X16(r, m), TWS2[((m) - 1) * 16 + j])
    ST2(1); ST2(2); ST2(3); ST2(4); ST2(5); ST2(6); ST2(7); ST2(8);
    ST2(9); ST2(10); ST2(11); ST2(12); ST2(13); ST2(14); ST2(15);
#undef ST2
}

// fwd L=16 (q=1, no twiddles)
__device__ __forceinline__ void fwd_stage3(C* __restrict__ z, int t) {
    const int bl = t & 15, bh = t >> 4;
    const int Cb = bl | (((bl ^ bh) & 15) << 4) | (bh << 8);
    C r[16];
#pragma unroll
    for (int k = 0; k < 16; k++) r[k] = z[Cb ^ k];
    dft16<true>(r);
#pragma unroll
    for (int m = 0; m < 16; m++) z[Cb ^ m] = X16(r, m);
}

// inv L=16 (no twiddles)
__device__ __forceinline__ void inv_stage1(C* __restrict__ z, int t) {
    const int bl = t & 15, bh = t >> 4;
    const int Cb = bl | (((bl ^ bh) & 15) << 4) | (bh << 8);
    C r[16];
#pragma unroll
    for (int k = 0; k < 16; k++) r[k] = z[Cb ^ k];
    dft16<false>(r);
#pragma unroll
    for (int m = 0; m < 16; m++) z[Cb ^ m] = X16(r, m);
}

// inv L=256 (conj twiddles on inputs, from g_twS2)
__device__ __forceinline__ void inv_stage2(C* __restrict__ z, int t) {
    const int bb = t >> 4, j = t & 15;
    const int Cb = j | (bb << 4) | (bb << 8);
    C r[16];
    r[0] = z[Cb];
#define LD2(k) r[k] = cmulc(z[Cb ^ (17 * (k))], TWS2[((k) - 1) * 16 + j])
    LD2(1); LD2(2); LD2(3); LD2(4); LD2(5); LD2(6); LD2(7); LD2(8);
    LD2(9); LD2(10); LD2(11); LD2(12); LD2(13); LD2(14); LD2(15);
#undef LD2
    dft16<false>(r);
#pragma unroll
    for (int m = 0; m < 16; m++) z[Cb ^ (17 * m)] = X16(r, m);
}

// inv L=4096 (conj twiddles from g_twS1; only outputs k<8 kept): stores y to gmem, scaled.
__device__ __forceinline__ void inv_stage3(const C* __restrict__ z, C* __restrict__ dst, int t) {
    const int d0 = t & 15, d1 = (t >> 4) & 15;
    const int Cb = (d0 ^ d1) | (d1 << 4);
    C ae[8], ao[8];
    ae[0] = z[Cb];
#define LD3(k) { C v = cmulc(z[Cb ^ (((k) << 4) ^ ((k) << 8))], TWS1[((k) - 1) * 256 + t]); \
                 if ((k) & 1) ao[(k) >> 1] = v; else ae[(k) >> 1] = v; }
    LD3(1); LD3(2); LD3(3); LD3(4); LD3(5); LD3(6); LD3(7); LD3(8);
    LD3(9); LD3(10); LD3(11); LD3(12); LD3(13); LD3(14); LD3(15);
#undef LD3
    dft8i(ae);
    dft8i(ao);
#pragma unroll
    for (int k = 0; k < 8; k++) {
        C v = padd(ae[k], cmulK(ao[k], w16c(k), w16s(k)));
        dst[t + (k << 8)] = pmul(v, SCALEC);
    }
}

// ---------------- pointwise ------------------------------------------------------------

// folded operator: Zk' = P*Zk + Q*conj(Zm);  Zm' = -conj(Q*Zk) + S*Zm
__device__ __forceinline__ void pw2(C& Zk, C& Zm, C P, C Q, C S) {
    C zk0 = Zk;
    C cm = conjC(Zm);
    C nk = cmul_acc(Q, cm, cmul(P, zk0));
    C qz = cmul(Q, zk0);
    C nm = cmul_acc(S, Zm, negconjC(qz));
    Zk = nk;
    Zm = nm;
}

// fold (X1=Kf[kk], X2=Kf[M-kk], tw) -> (P, Q, S)
__device__ __forceinline__ void makePQS(C X1, C X2, C tw, C& P, C& Q, C& S) {
    float cc_, ss_;
    unpackC(tw, cc_, ss_);
    float al = 0.5f * (1.f + ss_), be = 0.5f * (1.f - ss_), ga = 0.5f * cc_;
    C K2c = conjC(X2);
    C AL = packC(al, al), BE = packC(be, be), GA = packC(ga, ga);
    P = pfma(BE, K2c, pmul(AL, X1));
    Q = muli(pmul(GA, psub(X1, K2c)));
    S = conjC(pfma(AL, K2c, pmul(BE, X1)));
}

// Hermitian unpack (kf): X1 = X[kk], X2 = X[4096-kk]
__device__ __forceinline__ void unpackX(C Zk, C Zm, C tw, C& X1, C& X2) {
    C cm = conjC(Zm);
    C E = pmul(HALFC, padd(Zk, cm));
    C D = psub(Zk, cm);
    C O = pmul(HALFC, mulmi(D));
    C OT = cmul(O, tw);
    X1 = padd(E, OT);
    X2 = conjC(psub(E, OT));
}

// ---------------- kernel spectra -------------------------------------------------------
__global__ __launch_bounds__(NT, 4) void kf_kernel(const float* __restrict__ kin) {
    __shared__ C z[M];
    const int h = blockIdx.x;
    const int tid = threadIdx.x;
    const C* krow2 = (const C*)(kin + (size_t)h * M);
    fwd_stage1(z, krow2, tid); __syncthreads();
    fwd_stage2(z, tid); __syncthreads();
    fwd_stage3(z, tid); __syncthreads();

    ulonglong2* KPQ = g_KfPQ + (size_t)h * NUNIT;
    C* KS = g_KfS + (size_t)h * NUNIT;
#pragma unroll
    for (int i = 0; i < 8; i++) {
        int t = tid + i * NT;
        if (t != NUNIT - 1) {
            C idx = g_idx[t];
            unsigned sp8 = (unsigned)idx, sq8 = (unsigned)(idx >> 32);
            C Zk = *(const C*)((const char*)z + sp8);
            C Zm = *(const C*)((const char*)z + sq8);
            C X1, X2, tw = TWU2[t];
            unpackX(Zk, Zm, tw, X1, X2);
            ulonglong2 v; C Sv;
            makePQS(X1, X2, tw, v.x, v.y, Sv);
            KPQ[t] = v;
            KS[t] = Sv;
        } else {
            float zr, zi;
            unpackC(z[0], zr, zi);
            ulonglong2 v;
            v.x = packC(zr + zi, zr - zi);     // (Kf[0].re, Kf[M].re)
            v.y = conjC(z[8]);                 // Kf[M/2]
            KPQ[NUNIT - 1] = v;
        }
    }
}

// ---------------- main conv (single row per CTA; same-h rows adjacent) ------------------
__global__ __launch_bounds__(NT, 4) void conv_kernel(const float* __restrict__ x,
                                                     float* __restrict__ y) {
    __shared__ C z[M];
    const int g = blockIdx.x;              // h-adjacent ordering for Kf L2 reuse
    const int h = g >> 2;
    const int b = g & 3;
    const int row = b * H + h;
    const int tid = threadIdx.x;
    const C* xrow2 = (const C*)(x + (size_t)row * M);
    C* yrow2 = (C*)(y + (size_t)row * M);

    fwd_stage1(z, xrow2, tid); __syncthreads();
    fwd_stage2(z, tid); __syncthreads();
    fwd_stage3(z, tid); __syncthreads();

    const ulonglong2* __restrict__ KPQ = g_KfPQ + (size_t)h * NUNIT;
    const C* __restrict__ KS = g_KfS + (size_t)h * NUNIT;
#pragma unroll
    for (int i = 0; i < 8; i++) {
        int t = tid + i * NT;
        ulonglong2 Kv = KPQ[t];
        C Sv = KS[t];
        C idx = g_idx[t];
        if (t != NUNIT - 1) {
            unsigned sp8 = (unsigned)idx, sq8 = (unsigned)(idx >> 32);
            C* zp = (C*)((char*)z + sp8);
            C* zq = (C*)((char*)z + sq8);
            C Zk = *zp, Zm = *zq;
            pw2(Zk, Zm, Kv.x, Kv.y, Sv);
            *zp = Zk;
            *zq = Zm;
        } else {
            float zr, zi, kc, kd;
            unpackC(z[0], zr, zi);
            unpackC(Kv.x, kc, kd);
            float Y0 = (zr + zi) * kc;
            float Ym = (zr - zi) * kd;
            z[0] = packC(0.5f * (Y0 + Ym), 0.5f * (Y0 - Ym));
            z[8] = cmulc(z[8], Kv.y);          // bin M/2
        }
    }
    __syncthreads();
    inv_stage1(z, tid); __syncthreads();
    inv_stage2(z, tid); __syncthreads();
    inv_stage3(z, yrow2, tid);
}

extern "C" void kernel_launch(void* const* d_in, const int* in_sizes, int n_in,
                              void* d_out, int out_size) {
    const float* x;
    const float* k;
    if (in_sizes[0] == B * H * M) {           // x is the larger tensor
        x = (const float*)d_in[0];
        k = (const float*)d_in[1];
    } else {
        x = (const float*)d_in[1];
        k = (const float*)d_in[0];
    }
    float* y = (float*)d_out;

    const int ninit = NUNIT + 15 * 256 + 15 * 16;
    init_twiddles<<<(ninit + 511) / 512, 512>>>();
    kf_kernel<<<H, NT>>>(k);
    conv_kernel<<<B * H, NT>>>(x, y);
}